// round 5
// baseline (speedup 1.0000x reference)
#include <cuda_runtime.h>
#include <cuda_bf16.h>
#include <math.h>

// ---------------------------------------------------------------------------
// DNABERT2-style encoder forward, fp32, fused flash attention.
// B=1, L=2048, E=768, H=12, HD=64, NL=4, FFN=2048, V=4096
// ---------------------------------------------------------------------------

#define L_   2048
#define E_   768
#define H_   12
#define HD_  64
#define NL_  4
#define FFN_ 2048
#define V_   4096
#define EPS_ 1e-5f

// -------------------- scratch (static device globals; no allocation) -------
__device__ float g_x   [L_ * E_];          // residual stream      (6.3 MB)
__device__ float g_h   [L_ * E_];          // LN output            (6.3 MB)
__device__ float g_tmp [L_ * E_];          // attn out / mlm hidden(6.3 MB)
__device__ float g_qkv [L_ * 3 * E_];      // (L, 2304)            (18.9 MB)
__device__ float g_u   [L_ * 2 * FFN_];    // ffn1 output          (33.6 MB)
__device__ float g_gg  [L_ * FFN_];        // geglu output         (16.8 MB)

// -------------------- helpers ----------------------------------------------
__device__ __forceinline__ float gelu_exact(float x) {
    return 0.5f * x * (1.0f + erff(x * 0.70710678118654752440f));
}

// -------------------- embedding gather --------------------------------------
__global__ void embed_kernel(const int* __restrict__ tokens,
                             const float* __restrict__ embed,
                             float* __restrict__ x) {
    int idx = blockIdx.x * blockDim.x + threadIdx.x;
    if (idx >= L_ * E_) return;
    int l = idx / E_;
    int e = idx - l * E_;
    x[idx] = embed[(long)tokens[l] * E_ + e];
}

// -------------------- layernorm (one block per token) -----------------------
__global__ void layernorm_kernel(const float* __restrict__ x,
                                 const float* __restrict__ g,
                                 const float* __restrict__ b,
                                 float* __restrict__ y) {
    __shared__ float red[32];
    int row = blockIdx.x;
    int tid = threadIdx.x;             // 256 threads
    const float* xr = x + (long)row * E_;
    float v[3];
    #pragma unroll
    for (int i = 0; i < 3; i++) v[i] = xr[tid + i * 256];

    float s = v[0] + v[1] + v[2];
    #pragma unroll
    for (int o = 16; o > 0; o >>= 1) s += __shfl_xor_sync(0xffffffffu, s, o);
    if ((tid & 31) == 0) red[tid >> 5] = s;
    __syncthreads();
    float mean = 0.f;
    #pragma unroll
    for (int i = 0; i < 8; i++) mean += red[i];
    mean *= (1.0f / E_);
    __syncthreads();

    float sq = 0.f;
    #pragma unroll
    for (int i = 0; i < 3; i++) { float d = v[i] - mean; sq += d * d; }
    #pragma unroll
    for (int o = 16; o > 0; o >>= 1) sq += __shfl_xor_sync(0xffffffffu, sq, o);
    if ((tid & 31) == 0) red[tid >> 5] = sq;
    __syncthreads();
    float var = 0.f;
    #pragma unroll
    for (int i = 0; i < 8; i++) var += red[i];
    var *= (1.0f / E_);
    float inv = rsqrtf(var + EPS_);

    float* yr = y + (long)row * E_;
    #pragma unroll
    for (int i = 0; i < 3; i++) {
        int e = tid + i * 256;
        yr[e] = (v[i] - mean) * inv * g[e] + b[e];
    }
}

// -------------------- GEGLU -------------------------------------------------
__global__ void geglu_kernel(const float* __restrict__ u, float* __restrict__ o) {
    int idx = blockIdx.x * blockDim.x + threadIdx.x;
    if (idx >= L_ * FFN_) return;
    int l = idx / FFN_;
    int f = idx - l * FFN_;
    float a = u[(long)l * (2 * FFN_) + f];
    float g = u[(long)l * (2 * FFN_) + FFN_ + f];
    o[idx] = a * gelu_exact(g);
}

// -------------------- fused flash attention ---------------------------------
// grid = (L/64, H). 128 threads. Q block 64 rows, K/V blocks of 32 keys.
// qkv layout: (L, 3E); Q at +0, K at +E, V at +2E; head h at +h*64.
// Writes o (L, E) already merged across heads (head offset h*64).
#define FBM 64
#define FBN 32

__global__ __launch_bounds__(128, 2)
void flash_attn_kernel(const float* __restrict__ qkv,
                       const int* __restrict__ mask,
                       float* __restrict__ o) {
    __shared__ float Qs[HD_][FBM + 4];   // [d][m], scaled
    __shared__ float Ks[HD_][FBN + 2];   // [d][n]
    __shared__ float Vs[FBN][HD_ + 4];   // [k][d]
    __shared__ float Ps[FBM][FBN + 1];   // [m][k]
    __shared__ float kp[FBN];

    int qb  = blockIdx.x;       // 0..31
    int h   = blockIdx.y;       // 0..11
    int tid = threadIdx.x;      // 0..127
    int ty  = tid >> 3;         // 0..15 -> 4 rows each
    int tx  = tid & 7;          // 0..7

    float slope = (h < 8) ? exp2f(-(float)(h + 1))
                          : exp2f(-0.5f * (float)(2 * (h - 8) + 1));
    const float scale = 0.125f;   // 1/sqrt(64)

    // load Q block (64x64), scaled, transposed into Qs[d][m]
    #pragma unroll
    for (int r = 0; r < 8; r++) {
        int idx = tid + r * 128;            // 0..1023
        int m = idx >> 4;                   // 0..63
        int d4 = idx & 15;                  // 0..15
        float4 q4 = *(const float4*)(qkv + (long)(qb * FBM + m) * (3 * E_)
                                     + h * HD_ + d4 * 4);
        Qs[d4 * 4 + 0][m] = q4.x * scale;
        Qs[d4 * 4 + 1][m] = q4.y * scale;
        Qs[d4 * 4 + 2][m] = q4.z * scale;
        Qs[d4 * 4 + 3][m] = q4.w * scale;
    }

    float acc[4][8] = {};
    float mi[4], li[4];
    #pragma unroll
    for (int i = 0; i < 4; i++) { mi[i] = -1e30f; li[i] = 0.f; }

    for (int kb = 0; kb < L_ / FBN; kb++) {
        // load K (transposed) and V (direct) for this key block
        #pragma unroll
        for (int r = 0; r < 4; r++) {
            int idx = tid + r * 128;        // 0..511
            int n = idx >> 4;               // 0..31
            int d4 = idx & 15;
            const float* kb_ = qkv + (long)(kb * FBN + n) * (3 * E_) + E_ + h * HD_;
            float4 k4 = *(const float4*)(kb_ + d4 * 4);
            Ks[d4 * 4 + 0][n] = k4.x; Ks[d4 * 4 + 1][n] = k4.y;
            Ks[d4 * 4 + 2][n] = k4.z; Ks[d4 * 4 + 3][n] = k4.w;
            const float* vb_ = qkv + (long)(kb * FBN + n) * (3 * E_) + 2 * E_ + h * HD_;
            *(float4*)&Vs[n][d4 * 4] = *(const float4*)(vb_ + d4 * 4);
        }
        if (tid < FBN) kp[tid] = (mask[kb * FBN + tid] == 0) ? 1.0f : 0.0f;
        __syncthreads();

        // S = (scaled Q) K^T, 4x4 per thread
        float S[4][4] = {};
        #pragma unroll
        for (int d = 0; d < HD_; d++) {
            float ra[4], rb[4];
            #pragma unroll
            for (int i = 0; i < 4; i++) ra[i] = Qs[d][ty * 4 + i];
            #pragma unroll
            for (int j = 0; j < 4; j++) rb[j] = Ks[d][tx * 4 + j];
            #pragma unroll
            for (int i = 0; i < 4; i++)
                #pragma unroll
                for (int j = 0; j < 4; j++)
                    S[i][j] = fmaf(ra[i], rb[j], S[i][j]);
        }
        // bias: alibi + key padding
        #pragma unroll
        for (int i = 0; i < 4; i++) {
            int m = qb * FBM + ty * 4 + i;
            #pragma unroll
            for (int j = 0; j < 4; j++) {
                int n = kb * FBN + tx * 4 + j;
                S[i][j] += slope * (float)(n - m) + kp[tx * 4 + j];
            }
        }
        // online softmax (row group = 8 consecutive lanes: same ty, tx 0..7)
        #pragma unroll
        for (int i = 0; i < 4; i++) {
            float mx = fmaxf(fmaxf(S[i][0], S[i][1]), fmaxf(S[i][2], S[i][3]));
            #pragma unroll
            for (int o2 = 1; o2 < 8; o2 <<= 1)
                mx = fmaxf(mx, __shfl_xor_sync(0xffffffffu, mx, o2));
            float nm = fmaxf(mi[i], mx);
            float corr = __expf(mi[i] - nm);
            float s = 0.f;
            #pragma unroll
            for (int j = 0; j < 4; j++) { S[i][j] = __expf(S[i][j] - nm); s += S[i][j]; }
            #pragma unroll
            for (int o2 = 1; o2 < 8; o2 <<= 1)
                s += __shfl_xor_sync(0xffffffffu, s, o2);
            li[i] = li[i] * corr + s;
            mi[i] = nm;
            #pragma unroll
            for (int j = 0; j < 8; j++) acc[i][j] *= corr;
            #pragma unroll
            for (int j = 0; j < 4; j++) Ps[ty * 4 + i][tx * 4 + j] = S[i][j];
        }
        __syncthreads();

        // O += P @ V  (thread covers rows ty*4+i, dims tx*8+j)
        #pragma unroll
        for (int k = 0; k < FBN; k++) {
            float ra[4], rb[8];
            #pragma unroll
            for (int i = 0; i < 4; i++) ra[i] = Ps[ty * 4 + i][k];
            #pragma unroll
            for (int j = 0; j < 8; j++) rb[j] = Vs[k][tx * 8 + j];
            #pragma unroll
            for (int i = 0; i < 4; i++)
                #pragma unroll
                for (int j = 0; j < 8; j++)
                    acc[i][j] = fmaf(ra[i], rb[j], acc[i][j]);
        }
        __syncthreads();
    }

    // normalize and write
    #pragma unroll
    for (int i = 0; i < 4; i++) {
        int m = qb * FBM + ty * 4 + i;
        float inv = 1.0f / li[i];
        #pragma unroll
        for (int j = 0; j < 8; j++)
            o[(long)m * E_ + h * HD_ + tx * 8 + j] = acc[i][j] * inv;
    }
}

// -------------------- tiled GEMM --------------------------------------------
// C[m,n] = sum_k A[m,k] * B[n,k]  (B is (N,K) row-major: "x @ W^T")
// epi: 0 = +bias, 1 = +bias+residual(C in-place), 2 = gelu(+bias)
#define BM 64
#define BN 64
#define BK 16

__global__ void gemm_kernel(const float* __restrict__ A,
                            const float* __restrict__ B,
                            const float* __restrict__ bias,
                            const float* resid,
                            float* C,
                            int M, int N, int K,
                            int epi) {
    __shared__ float As[BK][BM + 4];
    __shared__ float Bs[BK][BN + 4];

    int m0 = blockIdx.y * BM;
    int n0 = blockIdx.x * BN;
    int tid = threadIdx.x;            // 256
    int ar = tid >> 2;                // 0..63
    int ac = (tid & 3) * 4;           // 0,4,8,12
    int ty = tid >> 4;                // 0..15 (m micro)
    int tx = tid & 15;                // 0..15 (n micro)

    float acc[4][4] = {};

    for (int k0 = 0; k0 < K; k0 += BK) {
        float4 a4 = *(const float4*)(A + (long)(m0 + ar) * K + k0 + ac);
        As[ac + 0][ar] = a4.x; As[ac + 1][ar] = a4.y;
        As[ac + 2][ar] = a4.z; As[ac + 3][ar] = a4.w;
        float4 b4 = *(const float4*)(B + (long)(n0 + ar) * K + k0 + ac);
        Bs[ac + 0][ar] = b4.x; Bs[ac + 1][ar] = b4.y;
        Bs[ac + 2][ar] = b4.z; Bs[ac + 3][ar] = b4.w;
        __syncthreads();
        #pragma unroll
        for (int k = 0; k < BK; k++) {
            float ra[4], rb[4];
            *(float4*)ra = *(const float4*)&As[k][ty * 4];
            *(float4*)rb = *(const float4*)&Bs[k][tx * 4];
            #pragma unroll
            for (int i = 0; i < 4; i++)
                #pragma unroll
                for (int j = 0; j < 4; j++)
                    acc[i][j] = fmaf(ra[i], rb[j], acc[i][j]);
        }
        __syncthreads();
    }

    #pragma unroll
    for (int i = 0; i < 4; i++) {
        int m = m0 + ty * 4 + i;
        #pragma unroll
        for (int j = 0; j < 4; j++) {
            int n = n0 + tx * 4 + j;
            float v = acc[i][j] + bias[n];
            if (epi == 1) v += resid[(long)m * N + n];
            if (epi == 2) v = gelu_exact(v);
            C[(long)m * N + n] = v;
        }
    }
}

// ---------------------------------------------------------------------------
extern "C" void kernel_launch(void* const* d_in, const int* in_sizes, int n_in,
                              void* d_out, int out_size) {
    const int*   tokens   = (const int*)  d_in[0];
    const int*   attmask  = (const int*)  d_in[1];
    const float* embed    = (const float*)d_in[2];
    const float* norm1_g  = (const float*)d_in[3];
    const float* norm1_b  = (const float*)d_in[4];
    const float* in_w     = (const float*)d_in[5];
    const float* in_b     = (const float*)d_in[6];
    const float* out_w    = (const float*)d_in[7];
    const float* out_b    = (const float*)d_in[8];
    const float* ffn_g    = (const float*)d_in[9];
    const float* ffn_bt   = (const float*)d_in[10];
    const float* ffn_w1   = (const float*)d_in[11];
    const float* ffn_b1   = (const float*)d_in[12];
    const float* ffn_w2   = (const float*)d_in[13];
    const float* ffn_b2   = (const float*)d_in[14];
    const float* fin_g    = (const float*)d_in[15];
    const float* fin_b    = (const float*)d_in[16];
    const float* mlm_w1   = (const float*)d_in[17];
    const float* mlm_b1   = (const float*)d_in[18];
    const float* mlm_g    = (const float*)d_in[19];
    const float* mlm_bt   = (const float*)d_in[20];
    const float* mlm_w2   = (const float*)d_in[21];
    const float* mlm_b2   = (const float*)d_in[22];
    float* out = (float*)d_out;

    float *x, *h, *tmp, *qkv, *u, *gg;
    cudaGetSymbolAddress((void**)&x,   g_x);
    cudaGetSymbolAddress((void**)&h,   g_h);
    cudaGetSymbolAddress((void**)&tmp, g_tmp);
    cudaGetSymbolAddress((void**)&qkv, g_qkv);
    cudaGetSymbolAddress((void**)&u,   g_u);
    cudaGetSymbolAddress((void**)&gg,  g_gg);

    embed_kernel<<<(L_ * E_ + 255) / 256, 256>>>(tokens, embed, x);

    for (int i = 0; i < NL_; i++) {
        // ---- attention ----
        layernorm_kernel<<<L_, 256>>>(x, norm1_g + i * E_, norm1_b + i * E_, h);

        // qkv = h @ in_w[i]^T + in_b[i]    (2048 x 2304, K=768)
        gemm_kernel<<<dim3(3 * E_ / BN, L_ / BM), 256>>>(
            h, in_w + (long)i * 3 * E_ * E_, in_b + (long)i * 3 * E_,
            nullptr, qkv, L_, 3 * E_, E_, 0);

        // fused flash attention -> tmp (L, E)
        flash_attn_kernel<<<dim3(L_ / FBM, H_), 128>>>(qkv, attmask, tmp);

        // x = x + tmp @ out_w[i]^T + out_b[i]
        gemm_kernel<<<dim3(E_ / BN, L_ / BM), 256>>>(
            tmp, out_w + (long)i * E_ * E_, out_b + (long)i * E_,
            x, x, L_, E_, E_, 1);

        // ---- GEGLU FFN ----
        layernorm_kernel<<<L_, 256>>>(x, ffn_g + i * E_, ffn_bt + i * E_, h);

        gemm_kernel<<<dim3(2 * FFN_ / BN, L_ / BM), 256>>>(
            h, ffn_w1 + (long)i * 2 * FFN_ * E_, ffn_b1 + (long)i * 2 * FFN_,
            nullptr, u, L_, 2 * FFN_, E_, 0);

        geglu_kernel<<<(L_ * FFN_ + 255) / 256, 256>>>(u, gg);

        gemm_kernel<<<dim3(E_ / BN, L_ / BM), 256>>>(
            gg, ffn_w2 + (long)i * E_ * FFN_, ffn_b2 + (long)i * E_,
            x, x, L_, E_, FFN_, 1);
    }

    // ---- MLM head ----
    layernorm_kernel<<<L_, 256>>>(x, fin_g, fin_b, h);

    gemm_kernel<<<dim3(E_ / BN, L_ / BM), 256>>>(
        h, mlm_w1, mlm_b1, nullptr, tmp, L_, E_, E_, 2 /*gelu*/);

    layernorm_kernel<<<L_, 256>>>(tmp, mlm_g, mlm_bt, h);

    gemm_kernel<<<dim3(V_ / BN, L_ / BM), 256>>>(
        h, mlm_w2, mlm_b2, nullptr, out, L_, V_, E_, 0);
}

// round 7
// speedup vs baseline: 1.0351x; 1.0351x over previous
#include <cuda_runtime.h>
#include <cuda_bf16.h>
#include <math.h>
#include <stdint.h>

// ---------------------------------------------------------------------------
// DNABERT2-style encoder forward. 3xTF32 tensor-core GEMMs + fp32 flash attn.
// B=1, L=2048, E=768, H=12, HD=64, NL=4, FFN=2048, V=4096
// ---------------------------------------------------------------------------

#define L_   2048
#define E_   768
#define H_   12
#define HD_  64
#define NL_  4
#define FFN_ 2048
#define V_   4096
#define EPS_ 1e-5f

// -------------------- scratch (static device globals; no allocation) -------
__device__ float g_x   [L_ * E_];
__device__ float g_h   [L_ * E_];
__device__ float g_tmp [L_ * E_];
__device__ float g_qkv [L_ * 3 * E_];
__device__ float g_u   [L_ * 2 * FFN_];
__device__ float g_gg  [L_ * FFN_];

// -------------------- helpers ----------------------------------------------
__device__ __forceinline__ float gelu_exact(float x) {
    return 0.5f * x * (1.0f + erff(x * 0.70710678118654752440f));
}

__device__ __forceinline__ float to_tf32(float x) {
    asm("cvt.rna.tf32.f32 %0, %1;" : "=f"(x) : "f"(x));
    return x;
}

__device__ __forceinline__ void split_tf32(float x, float& hi, float& lo) {
    hi = to_tf32(x);
    lo = to_tf32(x - hi);
}

__device__ __forceinline__ void mma_tf32(float* c, const uint32_t* a, const uint32_t* b) {
    asm volatile(
        "mma.sync.aligned.m16n8k8.row.col.f32.tf32.tf32.f32 "
        "{%0,%1,%2,%3}, {%4,%5,%6,%7}, {%8,%9}, {%0,%1,%2,%3};\n"
        : "+f"(c[0]), "+f"(c[1]), "+f"(c[2]), "+f"(c[3])
        : "r"(a[0]), "r"(a[1]), "r"(a[2]), "r"(a[3]), "r"(b[0]), "r"(b[1]));
}

// -------------------- embedding gather --------------------------------------
__global__ void embed_kernel(const int* __restrict__ tokens,
                             const float* __restrict__ embed,
                             float* __restrict__ x) {
    int idx = blockIdx.x * blockDim.x + threadIdx.x;
    if (idx >= L_ * E_) return;
    int l = idx / E_;
    int e = idx - l * E_;
    x[idx] = embed[(long)tokens[l] * E_ + e];
}

// -------------------- layernorm (one block per token) -----------------------
__global__ void layernorm_kernel(const float* __restrict__ x,
                                 const float* __restrict__ g,
                                 const float* __restrict__ b,
                                 float* __restrict__ y) {
    __shared__ float red[32];
    int row = blockIdx.x;
    int tid = threadIdx.x;             // 256 threads
    const float* xr = x + (long)row * E_;
    float v[3];
    #pragma unroll
    for (int i = 0; i < 3; i++) v[i] = xr[tid + i * 256];

    float s = v[0] + v[1] + v[2];
    #pragma unroll
    for (int o = 16; o > 0; o >>= 1) s += __shfl_xor_sync(0xffffffffu, s, o);
    if ((tid & 31) == 0) red[tid >> 5] = s;
    __syncthreads();
    float mean = 0.f;
    #pragma unroll
    for (int i = 0; i < 8; i++) mean += red[i];
    mean *= (1.0f / E_);
    __syncthreads();

    float sq = 0.f;
    #pragma unroll
    for (int i = 0; i < 3; i++) { float d = v[i] - mean; sq += d * d; }
    #pragma unroll
    for (int o = 16; o > 0; o >>= 1) sq += __shfl_xor_sync(0xffffffffu, sq, o);
    if ((tid & 31) == 0) red[tid >> 5] = sq;
    __syncthreads();
    float var = 0.f;
    #pragma unroll
    for (int i = 0; i < 8; i++) var += red[i];
    var *= (1.0f / E_);
    float inv = rsqrtf(var + EPS_);

    float* yr = y + (long)row * E_;
    #pragma unroll
    for (int i = 0; i < 3; i++) {
        int e = tid + i * 256;
        yr[e] = (v[i] - mean) * inv * g[e] + b[e];
    }
}

// -------------------- GEGLU -------------------------------------------------
__global__ void geglu_kernel(const float* __restrict__ u, float* __restrict__ o) {
    int idx = blockIdx.x * blockDim.x + threadIdx.x;
    if (idx >= L_ * FFN_) return;
    int l = idx / FFN_;
    int f = idx - l * FFN_;
    float a = u[(long)l * (2 * FFN_) + f];
    float g = u[(long)l * (2 * FFN_) + FFN_ + f];
    o[idx] = a * gelu_exact(g);
}

// -------------------- fused flash attention (unchanged, verified) -----------
#define FBM 64
#define FBN 32

__global__ __launch_bounds__(128, 2)
void flash_attn_kernel(const float* __restrict__ qkv,
                       const int* __restrict__ mask,
                       float* __restrict__ o) {
    __shared__ float Qs[HD_][FBM + 4];
    __shared__ float Ks[HD_][FBN + 2];
    __shared__ float Vs[FBN][HD_ + 4];
    __shared__ float Ps[FBM][FBN + 1];
    __shared__ float kp[FBN];

    int qb  = blockIdx.x;
    int h   = blockIdx.y;
    int tid = threadIdx.x;
    int ty  = tid >> 3;
    int tx  = tid & 7;

    float slope = (h < 8) ? exp2f(-(float)(h + 1))
                          : exp2f(-0.5f * (float)(2 * (h - 8) + 1));
    const float scale = 0.125f;

    #pragma unroll
    for (int r = 0; r < 8; r++) {
        int idx = tid + r * 128;
        int m = idx >> 4;
        int d4 = idx & 15;
        float4 q4 = *(const float4*)(qkv + (long)(qb * FBM + m) * (3 * E_)
                                     + h * HD_ + d4 * 4);
        Qs[d4 * 4 + 0][m] = q4.x * scale;
        Qs[d4 * 4 + 1][m] = q4.y * scale;
        Qs[d4 * 4 + 2][m] = q4.z * scale;
        Qs[d4 * 4 + 3][m] = q4.w * scale;
    }

    float acc[4][8] = {};
    float mi[4], li[4];
    #pragma unroll
    for (int i = 0; i < 4; i++) { mi[i] = -1e30f; li[i] = 0.f; }

    for (int kb = 0; kb < L_ / FBN; kb++) {
        #pragma unroll
        for (int r = 0; r < 4; r++) {
            int idx = tid + r * 128;
            int n = idx >> 4;
            int d4 = idx & 15;
            const float* kb_ = qkv + (long)(kb * FBN + n) * (3 * E_) + E_ + h * HD_;
            float4 k4 = *(const float4*)(kb_ + d4 * 4);
            Ks[d4 * 4 + 0][n] = k4.x; Ks[d4 * 4 + 1][n] = k4.y;
            Ks[d4 * 4 + 2][n] = k4.z; Ks[d4 * 4 + 3][n] = k4.w;
            const float* vb_ = qkv + (long)(kb * FBN + n) * (3 * E_) + 2 * E_ + h * HD_;
            *(float4*)&Vs[n][d4 * 4] = *(const float4*)(vb_ + d4 * 4);
        }
        if (tid < FBN) kp[tid] = (mask[kb * FBN + tid] == 0) ? 1.0f : 0.0f;
        __syncthreads();

        float S[4][4] = {};
        #pragma unroll
        for (int d = 0; d < HD_; d++) {
            float ra[4], rb[4];
            #pragma unroll
            for (int i = 0; i < 4; i++) ra[i] = Qs[d][ty * 4 + i];
            #pragma unroll
            for (int j = 0; j < 4; j++) rb[j] = Ks[d][tx * 4 + j];
            #pragma unroll
            for (int i = 0; i < 4; i++)
                #pragma unroll
                for (int j = 0; j < 4; j++)
                    S[i][j] = fmaf(ra[i], rb[j], S[i][j]);
        }
        #pragma unroll
        for (int i = 0; i < 4; i++) {
            int m = qb * FBM + ty * 4 + i;
            #pragma unroll
            for (int j = 0; j < 4; j++) {
                int n = kb * FBN + tx * 4 + j;
                S[i][j] += slope * (float)(n - m) + kp[tx * 4 + j];
            }
        }
        #pragma unroll
        for (int i = 0; i < 4; i++) {
            float mx = fmaxf(fmaxf(S[i][0], S[i][1]), fmaxf(S[i][2], S[i][3]));
            #pragma unroll
            for (int o2 = 1; o2 < 8; o2 <<= 1)
                mx = fmaxf(mx, __shfl_xor_sync(0xffffffffu, mx, o2));
            float nm = fmaxf(mi[i], mx);
            float corr = __expf(mi[i] - nm);
            float s = 0.f;
            #pragma unroll
            for (int j = 0; j < 4; j++) { S[i][j] = __expf(S[i][j] - nm); s += S[i][j]; }
            #pragma unroll
            for (int o2 = 1; o2 < 8; o2 <<= 1)
                s += __shfl_xor_sync(0xffffffffu, s, o2);
            li[i] = li[i] * corr + s;
            mi[i] = nm;
            #pragma unroll
            for (int j = 0; j < 8; j++) acc[i][j] *= corr;
            #pragma unroll
            for (int j = 0; j < 4; j++) Ps[ty * 4 + i][tx * 4 + j] = S[i][j];
        }
        __syncthreads();

        #pragma unroll
        for (int k = 0; k < FBN; k++) {
            float ra[4], rb[8];
            #pragma unroll
            for (int i = 0; i < 4; i++) ra[i] = Ps[ty * 4 + i][k];
            #pragma unroll
            for (int j = 0; j < 8; j++) rb[j] = Vs[k][tx * 8 + j];
            #pragma unroll
            for (int i = 0; i < 4; i++)
                #pragma unroll
                for (int j = 0; j < 8; j++)
                    acc[i][j] = fmaf(ra[i], rb[j], acc[i][j]);
        }
        __syncthreads();
    }

    #pragma unroll
    for (int i = 0; i < 4; i++) {
        int m = qb * FBM + ty * 4 + i;
        float inv = 1.0f / li[i];
        #pragma unroll
        for (int j = 0; j < 8; j++)
            o[(long)m * E_ + h * HD_ + tx * 8 + j] = acc[i][j] * inv;
    }
}

// -------------------- 3xTF32 tensor-core GEMM -------------------------------
// C[m,n] = sum_k A[m,k] * B[n,k]   (B is (N,K) row-major: "x @ W^T")
// Error-compensated: A=Ah+Al, B=Bh+Bl (tf32 splits);
// C ≈ Ah·Bh + Ah·Bl + Al·Bh  (dropped Al·Bl term is O(2^-22)).
// epi: 0 = +bias, 1 = +bias+residual, 2 = gelu(+bias)
// Requirements: M % 128 == 0, N % 64 == 0, K % 16 == 0 (all shapes satisfy).
#define TBM 128
#define TBN 64
#define TBK 16

__global__ __launch_bounds__(256, 2)
void gemm_tf32_kernel(const float* __restrict__ A,
                      const float* __restrict__ B,
                      const float* __restrict__ bias,
                      const float* __restrict__ resid,
                      float* __restrict__ C,
                      int M, int N, int K, int epi) {
    __shared__ float Ah[2][TBK][TBM + 4];
    __shared__ float Al[2][TBK][TBM + 4];
    __shared__ float Bh[2][TBK][TBN + 4];
    __shared__ float Bl[2][TBK][TBN + 4];

    int tid  = threadIdx.x;
    int lane = tid & 31;
    int wid  = tid >> 5;           // 0..7
    int wm   = (wid & 3) * 32;     // warp row offset in tile
    int wn   = (wid >> 2) * 32;    // warp col offset in tile
    int g    = lane >> 2;          // 0..7
    int tg   = lane & 3;           // 0..3

    int m0 = blockIdx.y * TBM;
    int n0 = blockIdx.x * TBN;

    int arow = tid >> 2;           // 0..63 (A rows arow, arow+64)
    int ac4  = (tid & 3) * 4;      // k-offset within tile
    int brow = tid >> 2;           // 0..63 (B row n)
    int bc4  = (tid & 3) * 4;

    float acc[2][4][4];
    #pragma unroll
    for (int i = 0; i < 2; i++)
        #pragma unroll
        for (int j = 0; j < 4; j++)
            #pragma unroll
            for (int q = 0; q < 4; q++) acc[i][j][q] = 0.f;

    const int KT = K / TBK;

    // ---- load tile 0 ----
    {
        #pragma unroll
        for (int r = 0; r < 2; r++) {
            int m = arow + r * 64;
            float4 a4 = *(const float4*)(A + (long)(m0 + m) * K + ac4);
            float hi, lo;
            split_tf32(a4.x, hi, lo); Ah[0][ac4 + 0][m] = hi; Al[0][ac4 + 0][m] = lo;
            split_tf32(a4.y, hi, lo); Ah[0][ac4 + 1][m] = hi; Al[0][ac4 + 1][m] = lo;
            split_tf32(a4.z, hi, lo); Ah[0][ac4 + 2][m] = hi; Al[0][ac4 + 2][m] = lo;
            split_tf32(a4.w, hi, lo); Ah[0][ac4 + 3][m] = hi; Al[0][ac4 + 3][m] = lo;
        }
        float4 b4 = *(const float4*)(B + (long)(n0 + brow) * K + bc4);
        float hi, lo;
        split_tf32(b4.x, hi, lo); Bh[0][bc4 + 0][brow] = hi; Bl[0][bc4 + 0][brow] = lo;
        split_tf32(b4.y, hi, lo); Bh[0][bc4 + 1][brow] = hi; Bl[0][bc4 + 1][brow] = lo;
        split_tf32(b4.z, hi, lo); Bh[0][bc4 + 2][brow] = hi; Bl[0][bc4 + 2][brow] = lo;
        split_tf32(b4.w, hi, lo); Bh[0][bc4 + 3][brow] = hi; Bl[0][bc4 + 3][brow] = lo;
    }
    __syncthreads();

    for (int kt = 0; kt < KT; kt++) {
        int cur = kt & 1;

        // prefetch next tile into registers
        float4 na0, na1, nb;
        if (kt + 1 < KT) {
            int k0 = (kt + 1) * TBK;
            na0 = *(const float4*)(A + (long)(m0 + arow) * K + k0 + ac4);
            na1 = *(const float4*)(A + (long)(m0 + arow + 64) * K + k0 + ac4);
            nb  = *(const float4*)(B + (long)(n0 + brow) * K + k0 + bc4);
        }

        // compute on current tile
        #pragma unroll
        for (int kk = 0; kk < TBK; kk += 8) {
            uint32_t ah[2][4], al[2][4], bh[4][2], bl[4][2];
            #pragma unroll
            for (int mt = 0; mt < 2; mt++) {
                int m = wm + mt * 16 + g;
                ah[mt][0] = __float_as_uint(Ah[cur][kk + tg    ][m]);
                ah[mt][1] = __float_as_uint(Ah[cur][kk + tg    ][m + 8]);
                ah[mt][2] = __float_as_uint(Ah[cur][kk + tg + 4][m]);
                ah[mt][3] = __float_as_uint(Ah[cur][kk + tg + 4][m + 8]);
                al[mt][0] = __float_as_uint(Al[cur][kk + tg    ][m]);
                al[mt][1] = __float_as_uint(Al[cur][kk + tg    ][m + 8]);
                al[mt][2] = __float_as_uint(Al[cur][kk + tg + 4][m]);
                al[mt][3] = __float_as_uint(Al[cur][kk + tg + 4][m + 8]);
            }
            #pragma unroll
            for (int nt = 0; nt < 4; nt++) {
                int n = wn + nt * 8 + g;
                bh[nt][0] = __float_as_uint(Bh[cur][kk + tg    ][n]);
                bh[nt][1] = __float_as_uint(Bh[cur][kk + tg + 4][n]);
                bl[nt][0] = __float_as_uint(Bl[cur][kk + tg    ][n]);
                bl[nt][1] = __float_as_uint(Bl[cur][kk + tg + 4][n]);
            }
            #pragma unroll
            for (int mt = 0; mt < 2; mt++)
                #pragma unroll
                for (int nt = 0; nt < 4; nt++) {
                    mma_tf32(acc[mt][nt], al[mt], bh[nt]);   // Al*Bh (small)
                    mma_tf32(acc[mt][nt], ah[mt], bl[nt]);   // Ah*Bl (small)
                    mma_tf32(acc[mt][nt], ah[mt], bh[nt]);   // Ah*Bh (main)
                }
        }

        // store prefetched tile into the other buffer
        if (kt + 1 < KT) {
            int nxt = cur ^ 1;
            float hi, lo;
            split_tf32(na0.x, hi, lo); Ah[nxt][ac4 + 0][arow] = hi; Al[nxt][ac4 + 0][arow] = lo;
            split_tf32(na0.y, hi, lo); Ah[nxt][ac4 + 1][arow] = hi; Al[nxt][ac4 + 1][arow] = lo;
            split_tf32(na0.z, hi, lo); Ah[nxt][ac4 + 2][arow] = hi; Al[nxt][ac4 + 2][arow] = lo;
            split_tf32(na0.w, hi, lo); Ah[nxt][ac4 + 3][arow] = hi; Al[nxt][ac4 + 3][arow] = lo;
            split_tf32(na1.x, hi, lo); Ah[nxt][ac4 + 0][arow + 64] = hi; Al[nxt][ac4 + 0][arow + 64] = lo;
            split_tf32(na1.y, hi, lo); Ah[nxt][ac4 + 1][arow + 64] = hi; Al[nxt][ac4 + 1][arow + 64] = lo;
            split_tf32(na1.z, hi, lo); Ah[nxt][ac4 + 2][arow + 64] = hi; Al[nxt][ac4 + 2][arow + 64] = lo;
            split_tf32(na1.w, hi, lo); Ah[nxt][ac4 + 3][arow + 64] = hi; Al[nxt][ac4 + 3][arow + 64] = lo;
            split_tf32(nb.x, hi, lo);  Bh[nxt][bc4 + 0][brow] = hi; Bl[nxt][bc4 + 0][brow] = lo;
            split_tf32(nb.y, hi, lo);  Bh[nxt][bc4 + 1][brow] = hi; Bl[nxt][bc4 + 1][brow] = lo;
            split_tf32(nb.z, hi, lo);  Bh[nxt][bc4 + 2][brow] = hi; Bl[nxt][bc4 + 2][brow] = lo;
            split_tf32(nb.w, hi, lo);  Bh[nxt][bc4 + 3][brow] = hi; Bl[nxt][bc4 + 3][brow] = lo;
            __syncthreads();
        }
    }

    // ---- epilogue ----
    #pragma unroll
    for (int mt = 0; mt < 2; mt++) {
        #pragma unroll
        for (int nt = 0; nt < 4; nt++) {
            int c = n0 + wn + nt * 8 + 2 * tg;
            float b0 = bias[c], b1 = bias[c + 1];
            #pragma unroll
            for (int hf = 0; hf < 2; hf++) {
                int r = m0 + wm + mt * 16 + g + hf * 8;
                float v0 = acc[mt][nt][hf * 2 + 0] + b0;
                float v1 = acc[mt][nt][hf * 2 + 1] + b1;
                if (epi == 1) {
                    v0 += resid[(long)r * N + c];
                    v1 += resid[(long)r * N + c + 1];
                }
                if (epi == 2) { v0 = gelu_exact(v0); v1 = gelu_exact(v1); }
                *(float2*)(C + (long)r * N + c) = make_float2(v0, v1);
            }
        }
    }
}

// ---------------------------------------------------------------------------
extern "C" void kernel_launch(void* const* d_in, const int* in_sizes, int n_in,
                              void* d_out, int out_size) {
    const int*   tokens   = (const int*)  d_in[0];
    const int*   attmask  = (const int*)  d_in[1];
    const float* embed    = (const float*)d_in[2];
    const float* norm1_g  = (const float*)d_in[3];
    const float* norm1_b  = (const float*)d_in[4];
    const float* in_w     = (const float*)d_in[5];
    const float* in_b     = (const float*)d_in[6];
    const float* out_w    = (const float*)d_in[7];
    const float* out_b    = (const float*)d_in[8];
    const float* ffn_g    = (const float*)d_in[9];
    const float* ffn_bt   = (const float*)d_in[10];
    const float* ffn_w1   = (const float*)d_in[11];
    const float* ffn_b1   = (const float*)d_in[12];
    const float* ffn_w2   = (const float*)d_in[13];
    const float* ffn_b2   = (const float*)d_in[14];
    const float* fin_g    = (const float*)d_in[15];
    const float* fin_b    = (const float*)d_in[16];
    const float* mlm_w1   = (const float*)d_in[17];
    const float* mlm_b1   = (const float*)d_in[18];
    const float* mlm_g    = (const float*)d_in[19];
    const float* mlm_bt   = (const float*)d_in[20];
    const float* mlm_w2   = (const float*)d_in[21];
    const float* mlm_b2   = (const float*)d_in[22];
    float* out = (float*)d_out;

    float *x, *h, *tmp, *qkv, *u, *gg;
    cudaGetSymbolAddress((void**)&x,   g_x);
    cudaGetSymbolAddress((void**)&h,   g_h);
    cudaGetSymbolAddress((void**)&tmp, g_tmp);
    cudaGetSymbolAddress((void**)&qkv, g_qkv);
    cudaGetSymbolAddress((void**)&u,   g_u);
    cudaGetSymbolAddress((void**)&gg,  g_gg);

    embed_kernel<<<(L_ * E_ + 255) / 256, 256>>>(tokens, embed, x);

    for (int i = 0; i < NL_; i++) {
        // ---- attention ----
        layernorm_kernel<<<L_, 256>>>(x, norm1_g + i * E_, norm1_b + i * E_, h);

        gemm_tf32_kernel<<<dim3(3 * E_ / TBN, L_ / TBM), 256>>>(
            h, in_w + (long)i * 3 * E_ * E_, in_b + (long)i * 3 * E_,
            nullptr, qkv, L_, 3 * E_, E_, 0);

        flash_attn_kernel<<<dim3(L_ / FBM, H_), 128>>>(qkv, attmask, tmp);

        gemm_tf32_kernel<<<dim3(E_ / TBN, L_ / TBM), 256>>>(
            tmp, out_w + (long)i * E_ * E_, out_b + (long)i * E_,
            x, x, L_, E_, E_, 1);

        // ---- GEGLU FFN ----
        layernorm_kernel<<<L_, 256>>>(x, ffn_g + i * E_, ffn_bt + i * E_, h);

        gemm_tf32_kernel<<<dim3(2 * FFN_ / TBN, L_ / TBM), 256>>>(
            h, ffn_w1 + (long)i * 2 * FFN_ * E_, ffn_b1 + (long)i * 2 * FFN_,
            nullptr, u, L_, 2 * FFN_, E_, 0);

        geglu_kernel<<<(L_ * FFN_ + 255) / 256, 256>>>(u, gg);

        gemm_tf32_kernel<<<dim3(E_ / TBN, L_ / TBM), 256>>>(
            gg, ffn_w2 + (long)i * E_ * FFN_, ffn_b2 + (long)i * E_,
            x, x, L_, E_, FFN_, 1);
    }

    // ---- MLM head ----
    layernorm_kernel<<<L_, 256>>>(x, fin_g, fin_b, h);

    gemm_tf32_kernel<<<dim3(E_ / TBN, L_ / TBM), 256>>>(
        h, mlm_w1, mlm_b1, nullptr, tmp, L_, E_, E_, 2);

    layernorm_kernel<<<L_, 256>>>(tmp, mlm_g, mlm_bt, h);

    gemm_tf32_kernel<<<dim3(V_ / TBN, L_ / TBM), 256>>>(
        h, mlm_w2, mlm_b2, nullptr, out, L_, V_, E_, 0);
}